// round 6
// baseline (speedup 1.0000x reference)
#include <cuda_runtime.h>
#include <cuda_bf16.h>

// Problem shape (fixed by the dataset)
#define N_DIM 8
#define V_DIM 3
#define C_DIM 24
#define T_DIM 8
#define H_DIM 128
#define W_DIM 128

constexpr int HW      = H_DIM * W_DIM;         // 16384
constexpr int VCT     = V_DIM * C_DIM * T_DIM; // 576 slabs per n
constexpr int CHUNK   = 2048;                  // hw positions per block
constexpr int NCHUNK  = HW / CHUNK;            // 8
constexpr int GROUP   = 48;                    // slabs per block (6 c-values x 8 t)
constexpr int NGROUP  = VCT / GROUP;           // 12
constexpr int MAIN_BLOCKS  = N_DIM * NCHUNK * NGROUP; // 768
constexpr int TOTAL_BLOCKS = MAIN_BLOCKS + N_DIM;     // +8 mask-sum blocks
constexpr int THREADS = 256;

// Deterministic reduction scratch (static device globals — no allocation)
__device__ float g_part[MAIN_BLOCKS];
__device__ float g_maskpart[N_DIM];

__global__ __launch_bounds__(THREADS, 5)
void anomaly_l1_main(const float* __restrict__ pred,
                     const int*   __restrict__ mask,
                     const float* __restrict__ vq0)
{
    __shared__ float sred[THREADS / 32];

    const int b   = blockIdx.x;
    const int tid = threadIdx.x;

    if (b >= MAIN_BLOCKS) {
        // ---- tail blocks: per-n mask sums (denominator) ----
        const int n = b - MAIN_BLOCKS;
        const int4* m4 = reinterpret_cast<const int4*>(mask + n * HW);
        int s = 0;
        #pragma unroll
        for (int k = 0; k < HW / 4 / THREADS; ++k) {   // 16 int4 per thread
            int4 v = m4[tid + k * THREADS];
            s += v.x + v.y + v.z + v.w;
        }
        #pragma unroll
        for (int o = 16; o; o >>= 1) s += __shfl_xor_sync(0xFFFFFFFFu, s, o);
        if ((tid & 31) == 0) sred[tid >> 5] = (float)s;
        __syncthreads();
        if (tid == 0) {
            float t = 0.f;
            #pragma unroll
            for (int i = 0; i < THREADS / 32; ++i) t += sred[i];
            g_maskpart[n] = t;
        }
        cudaTriggerProgrammaticLaunchCompletion();
        return;
    }

    // ---- main blocks: decode (n, chunk, group) ----
    const int group = b % NGROUP;
    const int chunk = (b / NGROUP) % NCHUNK;
    const int n     = b / (NGROUP * NCHUNK);

    // Weights live in REGISTERS: this thread touches the same 8 hw positions
    // in every one of its 48 slabs. No SMEM staging, no LDS in the hot loop.
    float4 w0, w1;
    {
        const int4* m4 = reinterpret_cast<const int4*>(mask + n * HW + chunk * CHUNK);
        int4 a = m4[tid];
        int4 c = m4[tid + THREADS];
        w0 = make_float4(1.f - (float)a.x, 1.f - (float)a.y,
                         1.f - (float)a.z, 1.f - (float)a.w);
        w1 = make_float4(1.f - (float)c.x, 1.f - (float)c.y,
                         1.f - (float)c.z, 1.f - (float)c.w);
    }

    // Slabs group*48 .. group*48+47 span c = (group&3)*6 + j, j=0..5 (no wrap:
    // (group&3)*6+5 <= 23), each c for 8 consecutive t.
    const int c0 = (group & 3) * 6;
    const int slab0 = group * GROUP;
    const float* base = pred + ((size_t)n * VCT + slab0) * (size_t)HW
                             + (size_t)chunk * CHUNK;

    float acc = 0.f;
    #pragma unroll 1
    for (int j = 0; j < 6; ++j) {
        const float vq = __ldg(vq0 + c0 + j);          // L1-resident
        const float* jb = base + (size_t)(j * 8) * HW;
        #pragma unroll
        for (int t = 0; t < 8; ++t) {                  // 16 batched LDG.128
            const float4* p = reinterpret_cast<const float4*>(jb + (size_t)t * HW);
            float4 x0 = p[tid];
            float4 x1 = p[tid + THREADS];
            acc = fmaf(fabsf(x0.x - vq), w0.x, acc);
            acc = fmaf(fabsf(x0.y - vq), w0.y, acc);
            acc = fmaf(fabsf(x0.z - vq), w0.z, acc);
            acc = fmaf(fabsf(x0.w - vq), w0.w, acc);
            acc = fmaf(fabsf(x1.x - vq), w1.x, acc);
            acc = fmaf(fabsf(x1.y - vq), w1.y, acc);
            acc = fmaf(fabsf(x1.z - vq), w1.z, acc);
            acc = fmaf(fabsf(x1.w - vq), w1.w, acc);
        }
    }

    #pragma unroll
    for (int o = 16; o; o >>= 1) acc += __shfl_xor_sync(0xFFFFFFFFu, acc, o);
    if ((tid & 31) == 0) sred[tid >> 5] = acc;
    __syncthreads();
    if (tid == 0) {
        float t = 0.f;
        #pragma unroll
        for (int i = 0; i < THREADS / 32; ++i) t += sred[i];
        g_part[b] = t;
    }
    cudaTriggerProgrammaticLaunchCompletion();
}

__global__ __launch_bounds__(THREADS)
void anomaly_l1_final(float* __restrict__ out)
{
    __shared__ float sred[THREADS / 32];
    const int tid = threadIdx.x;

    // PDL: launch ramp overlaps the main kernel; this blocks until the main
    // grid completes (ordering + visibility), then consumes the partials.
    cudaGridDependencySynchronize();

    float a = 0.f;
    for (int i = tid; i < MAIN_BLOCKS; i += THREADS) a += g_part[i];
    #pragma unroll
    for (int o = 16; o; o >>= 1) a += __shfl_xor_sync(0xFFFFFFFFu, a, o);
    if ((tid & 31) == 0) sred[tid >> 5] = a;
    __syncthreads();
    if (tid == 0) {
        float num = 0.f;
        #pragma unroll
        for (int i = 0; i < THREADS / 32; ++i) num += sred[i];
        float msum = 0.f;
        #pragma unroll
        for (int i = 0; i < N_DIM; ++i) msum += g_maskpart[i];
        double sumw = (double)N_DIM * HW - (double)msum;  // sum of weights over (N,H,W)
        double den  = sumw * (double)VCT;
        out[0] = (float)((double)num / den);
    }
}

extern "C" void kernel_launch(void* const* d_in, const int* in_sizes, int n_in,
                              void* d_out, int out_size)
{
    const float* pred = (const float*)d_in[0];   // (N,V,C,T,H,W) fp32
    const int*   mask = (const int*)  d_in[1];   // (N,H,W) int32
    const float* vq0  = (const float*)d_in[2];   // (1,C) fp32
    float* out = (float*)d_out;

    anomaly_l1_main<<<TOTAL_BLOCKS, THREADS>>>(pred, mask, vq0);

    // Reduction tail with Programmatic Dependent Launch: launch latency
    // overlaps the main kernel's final wave.
    cudaLaunchConfig_t cfg = {};
    cfg.gridDim  = dim3(1, 1, 1);
    cfg.blockDim = dim3(THREADS, 1, 1);
    cfg.dynamicSmemBytes = 0;
    cfg.stream = 0;   // same (capturing) stream as the <<<>>> launch above
    cudaLaunchAttribute attr[1];
    attr[0].id = cudaLaunchAttributeProgrammaticStreamSerialization;
    attr[0].val.programmaticStreamSerializationAllowed = 1;
    cfg.attrs = attr;
    cfg.numAttrs = 1;
    cudaError_t e = cudaLaunchKernelEx(&cfg, anomaly_l1_final, out);
    if (e != cudaSuccess) {
        anomaly_l1_final<<<1, THREADS>>>(out);   // correctness fallback
    }
}

// round 7
// speedup vs baseline: 1.1657x; 1.1657x over previous
#include <cuda_runtime.h>
#include <cuda_bf16.h>

// Problem shape (fixed by the dataset)
#define N_DIM 8
#define V_DIM 3
#define C_DIM 24
#define T_DIM 8
#define H_DIM 128
#define W_DIM 128

constexpr int HW      = H_DIM * W_DIM;         // 16384
constexpr int VCT     = V_DIM * C_DIM * T_DIM; // 576 slabs per n
constexpr int CHUNK   = 2048;                  // hw positions per block
constexpr int NCHUNK  = HW / CHUNK;            // 8
constexpr int GROUP   = 64;                    // slabs per block (8 c x 8 t, within one v)
constexpr int NGROUP  = VCT / GROUP;           // 9
constexpr int MAIN_BLOCKS  = N_DIM * NCHUNK * NGROUP; // 576
constexpr int TOTAL_BLOCKS = MAIN_BLOCKS + N_DIM;     // 584  (<= 4/SM * 148 = 592: ONE wave)
constexpr int THREADS = 256;

// Deterministic reduction scratch (static device globals — no allocation)
__device__ float g_part[MAIN_BLOCKS];
__device__ float g_maskpart[N_DIM];

__global__ __launch_bounds__(THREADS, 4)     // 64-reg budget: no spills, 4 blocks/SM
void anomaly_l1_main(const float* __restrict__ pred,
                     const int*   __restrict__ mask,
                     const float* __restrict__ vq0)
{
    __shared__ float sred[THREADS / 32];

    const int b   = blockIdx.x;
    const int tid = threadIdx.x;

    if (b >= MAIN_BLOCKS) {
        // ---- tail blocks: per-n mask sums (denominator) ----
        const int n = b - MAIN_BLOCKS;
        const int4* m4 = reinterpret_cast<const int4*>(mask + n * HW);
        int s = 0;
        #pragma unroll
        for (int k = 0; k < HW / 4 / THREADS; ++k) {   // 16 int4 per thread
            int4 v = m4[tid + k * THREADS];
            s += v.x + v.y + v.z + v.w;
        }
        #pragma unroll
        for (int o = 16; o; o >>= 1) s += __shfl_xor_sync(0xFFFFFFFFu, s, o);
        if ((tid & 31) == 0) sred[tid >> 5] = (float)s;
        __syncthreads();
        if (tid == 0) {
            float t = 0.f;
            #pragma unroll
            for (int i = 0; i < THREADS / 32; ++i) t += sred[i];
            g_maskpart[n] = t;
        }
        cudaTriggerProgrammaticLaunchCompletion();
        return;
    }

    // ---- main blocks: decode (n, chunk, group) ----
    const int group = b % NGROUP;                  // 0..8
    const int chunk = (b / NGROUP) % NCHUNK;       // 0..7
    const int n     = b / (NGROUP * NCHUNK);       // 0..7

    // Weights in REGISTERS: this thread touches the same 8 hw positions in all
    // 64 of its slabs. 8 regs total; no SMEM staging, no LDS in the hot loop.
    float4 w0, w1;
    {
        const int4* m4 = reinterpret_cast<const int4*>(mask + n * HW + chunk * CHUNK);
        int4 a = m4[tid];
        int4 c = m4[tid + THREADS];
        w0 = make_float4(1.f - (float)a.x, 1.f - (float)a.y,
                         1.f - (float)a.z, 1.f - (float)a.w);
        w1 = make_float4(1.f - (float)c.x, 1.f - (float)c.y,
                         1.f - (float)c.z, 1.f - (float)c.w);
    }

    // Slabs group*64 .. group*64+63: v = group/3, c = (group%3)*8 + j (j=0..7),
    // t = 0..7. 64*3 = 192 = one v-extent, so no v boundary is crossed.
    const int c0 = (group % 3) * 8;
    const float* base = pred + ((size_t)n * VCT + (size_t)group * GROUP) * (size_t)HW
                             + (size_t)chunk * CHUNK;

    float acc = 0.f;
    #pragma unroll 1
    for (int j = 0; j < 8; ++j) {                  // 8 c-values
        const float vq = __ldg(vq0 + c0 + j);      // L1-resident
        const float* jb = base + (size_t)(j * 8) * HW;
        #pragma unroll 1
        for (int th = 0; th < 2; ++th) {           // 2 half-batches of 4 t
            const float* tb = jb + (size_t)(th * 4) * HW;
            #pragma unroll
            for (int t = 0; t < 4; ++t) {          // 8 batched LDG.128 (32 data regs)
                const float4* p = reinterpret_cast<const float4*>(tb + (size_t)t * HW);
                float4 x0 = p[tid];
                float4 x1 = p[tid + THREADS];
                acc = fmaf(fabsf(x0.x - vq), w0.x, acc);
                acc = fmaf(fabsf(x0.y - vq), w0.y, acc);
                acc = fmaf(fabsf(x0.z - vq), w0.z, acc);
                acc = fmaf(fabsf(x0.w - vq), w0.w, acc);
                acc = fmaf(fabsf(x1.x - vq), w1.x, acc);
                acc = fmaf(fabsf(x1.y - vq), w1.y, acc);
                acc = fmaf(fabsf(x1.z - vq), w1.z, acc);
                acc = fmaf(fabsf(x1.w - vq), w1.w, acc);
            }
        }
    }

    #pragma unroll
    for (int o = 16; o; o >>= 1) acc += __shfl_xor_sync(0xFFFFFFFFu, acc, o);
    if ((tid & 31) == 0) sred[tid >> 5] = acc;
    __syncthreads();
    if (tid == 0) {
        float t = 0.f;
        #pragma unroll
        for (int i = 0; i < THREADS / 32; ++i) t += sred[i];
        g_part[b] = t;
    }
    cudaTriggerProgrammaticLaunchCompletion();
}

__global__ __launch_bounds__(THREADS)
void anomaly_l1_final(float* __restrict__ out)
{
    __shared__ float sred[THREADS / 32];
    const int tid = threadIdx.x;

    // PDL: launch ramp overlaps the main kernel; blocks here until the main
    // grid completes (ordering + visibility), then consumes the partials.
    cudaGridDependencySynchronize();

    float a = 0.f;
    for (int i = tid; i < MAIN_BLOCKS; i += THREADS) a += g_part[i];
    #pragma unroll
    for (int o = 16; o; o >>= 1) a += __shfl_xor_sync(0xFFFFFFFFu, a, o);
    if ((tid & 31) == 0) sred[tid >> 5] = a;
    __syncthreads();
    if (tid == 0) {
        float num = 0.f;
        #pragma unroll
        for (int i = 0; i < THREADS / 32; ++i) num += sred[i];
        float msum = 0.f;
        #pragma unroll
        for (int i = 0; i < N_DIM; ++i) msum += g_maskpart[i];
        double sumw = (double)N_DIM * HW - (double)msum;  // sum of weights over (N,H,W)
        double den  = sumw * (double)VCT;
        out[0] = (float)((double)num / den);
    }
}

extern "C" void kernel_launch(void* const* d_in, const int* in_sizes, int n_in,
                              void* d_out, int out_size)
{
    const float* pred = (const float*)d_in[0];   // (N,V,C,T,H,W) fp32
    const int*   mask = (const int*)  d_in[1];   // (N,H,W) int32
    const float* vq0  = (const float*)d_in[2];   // (1,C) fp32
    float* out = (float*)d_out;

    anomaly_l1_main<<<TOTAL_BLOCKS, THREADS>>>(pred, mask, vq0);

    // Reduction tail with Programmatic Dependent Launch: launch latency
    // overlaps the main kernel's final wave.
    cudaLaunchConfig_t cfg = {};
    cfg.gridDim  = dim3(1, 1, 1);
    cfg.blockDim = dim3(THREADS, 1, 1);
    cfg.dynamicSmemBytes = 0;
    cfg.stream = 0;   // same (capturing) stream as the <<<>>> launch above
    cudaLaunchAttribute attr[1];
    attr[0].id = cudaLaunchAttributeProgrammaticStreamSerialization;
    attr[0].val.programmaticStreamSerializationAllowed = 1;
    cfg.attrs = attr;
    cfg.numAttrs = 1;
    cudaError_t e = cudaLaunchKernelEx(&cfg, anomaly_l1_final, out);
    if (e != cudaSuccess) {
        anomaly_l1_final<<<1, THREADS>>>(out);   // correctness fallback
    }
}